// round 9
// baseline (speedup 1.0000x reference)
#include <cuda_runtime.h>
#include <cuda_fp16.h>

// Scratch: lgn transposed to channel-last [b][y][x][c] (4*64*64*64 f32 = 4MB)
__device__ float g_lgn_cl[4 * 64 * 64 * 64];

// ---------------------------------------------------------------------------
// Kernel 1: transpose lgn (B,C,H,W) -> (B,H,W,C), tiled via shared memory.
// ---------------------------------------------------------------------------
__global__ void transpose_lgn_kernel(const float* __restrict__ lgn) {
    __shared__ float sh[64][33];
    const int x0  = blockIdx.x * 32;
    const int y   = blockIdx.y;
    const int b   = blockIdx.z;
    const int tid = threadIdx.x;

    const int cL = tid >> 5, xL = tid & 31;
#pragma unroll
    for (int r = 0; r < 8; r++) {
        const int c = cL + r * 8;
        sh[c][xL] = lgn[(((b * 64 + c) * 64 + y) * 64) + x0 + xL];
    }
    __syncthreads();

    const int cS = tid & 63, xb = tid >> 6;
#pragma unroll
    for (int r = 0; r < 8; r++) {
        const int x = xb + r * 4;
        g_lgn_cl[(((b * 64 + y) * 64 + (x0 + x)) * 64) + cS] = sh[cS][x];
    }
}

__device__ __forceinline__ float dot4(float4 a, float4 b) {
    return a.x * b.x + a.y * b.y + a.z * b.z + a.w * b.w;
}
// two packed half2 words -> float4
__device__ __forceinline__ float4 rv(unsigned int a, unsigned int b) {
    const float2 lo = __half22float2(*(const __half2*)&a);
    const float2 hi = __half22float2(*(const __half2*)&b);
    return make_float4(lo.x, lo.y, hi.x, hi.y);
}
__device__ __forceinline__ unsigned int pk(float a, float b) {
    __half2 h = __floats2half2_rn(a, b);
    return *(unsigned int*)&h;
}

// ---------------------------------------------------------------------------
// Kernel 2: main fused compute.
// Block = 256 threads = 16 pixels x 16 nv.  Thread: pl = tid>>4, nv = tid&15.
// Smem = one 16KB fp32 phase buffer (coefy -> coefr -> coefx, serially) +
// 16KB fp16 tables (srh = folded Cy@Cr, sxh = Cx). 32KB total -> 5 blocks/SM
// at 51 regs (launch_bounds(256,5)) -> 40 warps, 62.5% occ.
// fp16 unit layout: uint4 unit (row, nv, h) holds rows {2h,2h+1} x 4 comps;
// physical index = row*32 + nv*2 + (h ^ ((nv>>2)&1))  -> conflict-free.
// Mainloop: branchless taps, validity folded into y-stage weights, per-row
// hoisted lgn gathers (MLP=3). Output staged via phase buffer, coalesced STG.
// ---------------------------------------------------------------------------
__global__ __launch_bounds__(256, 5) void seprot_main_kernel(
    const float* __restrict__ grid1, const float* __restrict__ grid2,
    const float* __restrict__ theta,
    const float* __restrict__ coefx, const float* __restrict__ coefy,
    const float* __restrict__ coefr, float* __restrict__ out)
{
    __shared__ float4 buf[1024];   // 16KB: fp32 phase buffer; later out-staging
    __shared__ uint4  tab[1024];   // 16KB: srh = tab[0..511], sxh = tab[512..]

    const int tid = threadIdx.x;

    const int nv   = tid & 15;
    const int swz  = (nv >> 1) & 3;
    const int hswz = (nv >> 2) & 1;
    const int nv4  = nv * 4;
    const int nv2  = nv * 2;
    const int pl   = tid >> 4;                 // pixel within block, 0..15
    const int P    = blockIdx.x * 16 + pl;     // global pixel id
    const int b    = blockIdx.x >> 8;          // 256 blocks per batch

    // transposed+swizzled cooperative load of one coef tensor into buf
    auto load_tab = [&](const float* __restrict__ src) {
#pragma unroll
        for (int it = 0; it < 16; it++) {
            const int g   = tid + it * 256;
            const int nvq = g >> 8;
            const int a   = (g >> 6) & 3;
            const int c2  = (g >> 4) & 3;
            const int n   = g & 15;
            const int entry = n * 64 + nvq * 4 + (a ^ ((nvq >> 1) & 3));
            ((float*)buf)[entry * 4 + c2] = src[g];
        }
    };

    // ---- phase A: coefy -> Cy (z interp; depends only on b,nv) ----
    load_tab(coefy);
    __syncthreads();

    const float zc  = theta[b] / 3.14159265358979323846f;
    const float gz  = (zc + 1.0f) * 8.0f - 0.5f;
    const float z0f = floorf(gz);
    const int   z0  = (int)z0f;
    const float wz1 = gz - z0f;
    const float wz0e = (z0 >= 0 && z0 <= 15) ? (1.0f - wz1) : 0.0f;
    const float wz1e = (z0 + 1 >= 0 && z0 + 1 <= 15) ? wz1 : 0.0f;
    const int iz0 = min(max(z0, 0), 15);
    const int iz1 = min(max(z0 + 1, 0), 15);
    const int zb0 = iz0 * 64 + nv4, zb1 = iz1 * 64 + nv4;

    float4 Cy[4];
#pragma unroll
    for (int kp = 0; kp < 4; kp++) {
        const float4 a0 = buf[zb0 + (kp ^ swz)];
        const float4 a1 = buf[zb1 + (kp ^ swz)];
        Cy[kp].x = wz0e * a0.x + wz1e * a1.x;
        Cy[kp].y = wz0e * a0.y + wz1e * a1.y;
        Cy[kp].z = wz0e * a0.z + wz1e * a1.z;
        Cy[kp].w = wz0e * a0.w + wz1e * a1.w;
    }
    __syncthreads();

    // ---- phase B: coefr -> fold srh = fp16(Cy @ Cr[row]) ----
    load_tab(coefr);
    __syncthreads();
    uint4* srh = tab;          // 512 uint4 = 8KB
    uint4* sxh = tab + 512;    // 512 uint4 = 8KB
    {
        const int row  = pl;               // 16 rows, one per pixel lane
        const int base = row * 64 + nv4;
        const float4 S0 = buf[base + (0 ^ swz)];
        const float4 S1 = buf[base + (1 ^ swz)];
        const float4 S2 = buf[base + (2 ^ swz)];
        const float4 S3 = buf[base + (3 ^ swz)];
        float4 R[4];
#pragma unroll
        for (int k = 0; k < 4; k++) {
            R[k].x = Cy[k].x*S0.x + Cy[k].y*S1.x + Cy[k].z*S2.x + Cy[k].w*S3.x;
            R[k].y = Cy[k].x*S0.y + Cy[k].y*S1.y + Cy[k].z*S2.y + Cy[k].w*S3.y;
            R[k].z = Cy[k].x*S0.z + Cy[k].y*S1.z + Cy[k].z*S2.z + Cy[k].w*S3.z;
            R[k].w = Cy[k].x*S0.w + Cy[k].y*S1.w + Cy[k].z*S2.w + Cy[k].w*S3.w;
        }
#pragma unroll
        for (int h = 0; h < 2; h++) {
            const float4 RA = R[2 * h];
            const float4 RB = R[2 * h + 1];
            uint4 u;
            u.x = pk(RA.x, RA.y); u.y = pk(RA.z, RA.w);
            u.z = pk(RB.x, RB.y); u.w = pk(RB.z, RB.w);
            srh[row * 32 + nv2 + (h ^ hswz)] = u;
        }
    }
    __syncthreads();

    // ---- phase C: coefx -> sxh = fp16(Cx) ----
    load_tab(coefx);
    __syncthreads();
    {
        const int row  = pl;
        const int base = row * 64 + nv4;
#pragma unroll
        for (int h = 0; h < 2; h++) {
            const float4 CA = buf[base + ((2 * h)     ^ swz)];
            const float4 CB = buf[base + ((2 * h + 1) ^ swz)];
            uint4 v;
            v.x = pk(CA.x, CA.y); v.y = pk(CA.z, CA.w);
            v.z = pk(CB.x, CB.y); v.w = pk(CB.z, CB.w);
            sxh[row * 32 + nv2 + (h ^ hswz)] = v;
        }
    }
    __syncthreads();

    // ---- mainloop ----
    const float2 g2 = ((const float2*)grid2)[P];   // warp-broadcast (2 addrs)
    const float fx = rintf((g2.x + 1.0f) * 32.0f - 0.5f);
    const float fy = rintf((g2.y + 1.0f) * 32.0f - 0.5f);
    const bool qv = (fx >= 0.0f) && (fx <= 63.0f) && (fy >= 0.0f) && (fy <= 63.0f);

    float acc0 = 0.0f, acc1 = 0.0f, acc2 = 0.0f, acc3 = 0.0f;

    if (qv) {
        const int qx = (int)fx, qy = (int)fy;
        const float4* lbase = (const float4*)g_lgn_cl + (size_t)b * (4096 * 16);
        const float2* g1base = (const float2*)grid1 + b * 4096;

        const int txc0 = min(max(qx - 1, 0), 63);
        const int txc1 = qx;
        const int txc2 = min(max(qx + 1, 0), 63);

#pragma unroll
        for (int di = -1; di <= 1; di++) {
            const int ty   = qy + di;
            const float rowv = ((unsigned)ty < 64u) ? 1.0f : 0.0f;
            const int tyc  = min(max(ty, 0), 63);

            float4 Lr[3];
            Lr[0] = lbase[(tyc * 64 + txc0) * 16 + nv];
            Lr[1] = lbase[(tyc * 64 + txc1) * 16 + nv];
            Lr[2] = lbase[(tyc * 64 + txc2) * 16 + nv];
            float2 g1r[3];
            g1r[0] = g1base[tyc * 64 + txc0];
            g1r[1] = g1base[tyc * 64 + txc1];
            g1r[2] = g1base[tyc * 64 + txc2];

#pragma unroll
            for (int dj = 0; dj < 3; dj++) {
                const int tx = qx + dj - 1;
                const float vm = rowv * (((unsigned)tx < 64u) ? 1.0f : 0.0f);

                const float dx = g2.x - g1r[dj].x;
                const float dy = g2.y - g1r[dj].y;

                // ---- x-axis interp over folded table ----
                const float gx  = (dx + 1.0f) * 8.0f - 0.5f;
                const float x0f = floorf(gx);
                const int   x0  = (int)x0f;
                const float wx1 = gx - x0f;
                const float wx0e = (x0 >= 0 && x0 <= 15) ? (1.0f - wx1) : 0.0f;
                const float wx1e = (x0 + 1 >= 0 && x0 + 1 <= 15) ? wx1 : 0.0f;
                const int ix0 = min(max(x0, 0), 15);
                const int ix1 = min(max(x0 + 1, 0), 15);

                const float4 L = Lr[dj];

                const uint4 U0a = srh[ix0 * 32 + nv2 + (0 ^ hswz)];
                const uint4 U0b = srh[ix0 * 32 + nv2 + (1 ^ hswz)];
                const uint4 U1a = srh[ix1 * 32 + nv2 + (0 ^ hswz)];
                const uint4 U1b = srh[ix1 * 32 + nv2 + (1 ^ hswz)];

                const float u0 = wx0e * dot4(rv(U0a.x, U0a.y), L)
                               + wx1e * dot4(rv(U1a.x, U1a.y), L);
                const float u1 = wx0e * dot4(rv(U0a.z, U0a.w), L)
                               + wx1e * dot4(rv(U1a.z, U1a.w), L);
                const float u2 = wx0e * dot4(rv(U0b.x, U0b.y), L)
                               + wx1e * dot4(rv(U1b.x, U1b.y), L);
                const float u3 = wx0e * dot4(rv(U0b.z, U0b.w), L)
                               + wx1e * dot4(rv(U1b.z, U1b.w), L);
                const float4 u4 = make_float4(u0, u1, u2, u3);

                // ---- y-axis interp over Cx, validity folded into weights ----
                const float gy  = (dy + 1.0f) * 8.0f - 0.5f;
                const float y0f = floorf(gy);
                const int   y0  = (int)y0f;
                const float wy1 = gy - y0f;
                const float wy0e = vm * ((y0 >= 0 && y0 <= 15) ? (1.0f - wy1) : 0.0f);
                const float wy1e = vm * ((y0 + 1 >= 0 && y0 + 1 <= 15) ? wy1 : 0.0f);
                const int iy0 = min(max(y0, 0), 15);
                const int iy1 = min(max(y0 + 1, 0), 15);

                const uint4 V0a = sxh[iy0 * 32 + nv2 + (0 ^ hswz)];
                const uint4 V0b = sxh[iy0 * 32 + nv2 + (1 ^ hswz)];
                const uint4 V1a = sxh[iy1 * 32 + nv2 + (0 ^ hswz)];
                const uint4 V1b = sxh[iy1 * 32 + nv2 + (1 ^ hswz)];

                acc0 += wy0e * dot4(rv(V0a.x, V0a.y), u4)
                      + wy1e * dot4(rv(V1a.x, V1a.y), u4);
                acc1 += wy0e * dot4(rv(V0a.z, V0a.w), u4)
                      + wy1e * dot4(rv(V1a.z, V1a.w), u4);
                acc2 += wy0e * dot4(rv(V0b.x, V0b.y), u4)
                      + wy1e * dot4(rv(V1b.x, V1b.y), u4);
                acc3 += wy0e * dot4(rv(V0b.z, V0b.w), u4)
                      + wy1e * dot4(rv(V1b.z, V1b.w), u4);
            }
        }
    }

    // ---- stage outputs in smem (aliasing buf), then coalesced stores ----
    float* so = (float*)buf;           // needs 64*17 = 1088 floats < 4096 avail
    __syncthreads();                   // ensure phase-C reads of buf are done
    so[(nv4 + 0) * 17 + pl] = acc0;
    so[(nv4 + 1) * 17 + pl] = acc1;
    so[(nv4 + 2) * 17 + pl] = acc2;
    so[(nv4 + 3) * 17 + pl] = acc3;
    __syncthreads();

    // out layout (B, 64, 64, 64): 16 consecutive pixels per block, same batch
    const int rem0 = (blockIdx.x & 255) * 16;
    float* obase = out + (size_t)b * 64 * 4096 + rem0;
#pragma unroll
    for (int i2 = 0; i2 < 4; i2++) {
        const int idx = tid + i2 * 256;
        const int c = idx >> 4, px = idx & 15;
        obase[(size_t)c * 4096 + px] = so[c * 17 + px];
    }
}

extern "C" void kernel_launch(void* const* d_in, const int* in_sizes, int n_in,
                              void* d_out, int out_size) {
    const float* grid1 = (const float*)d_in[0];
    const float* grid2 = (const float*)d_in[1];
    const float* theta = (const float*)d_in[2];
    const float* lgn   = (const float*)d_in[3];
    const float* coefx = (const float*)d_in[4];
    const float* coefy = (const float*)d_in[5];
    const float* coefr = (const float*)d_in[6];
    float* out = (float*)d_out;

    transpose_lgn_kernel<<<dim3(2, 64, 4), 256>>>(lgn);
    seprot_main_kernel<<<1024, 256>>>(grid1, grid2, theta, coefx, coefy, coefr, out);
}

// round 10
// speedup vs baseline: 1.4947x; 1.4947x over previous
#include <cuda_runtime.h>
#include <cuda_fp16.h>

// Scratch: lgn transposed to channel-last [b][y][x][c] (4*64*64*64 f32 = 4MB)
__device__ float g_lgn_cl[4 * 64 * 64 * 64];
// Precomputed fp16 tables per batch: [b][0..511]=srh (folded Cy@Cr), [512..1023]=sxh (Cx)
__device__ uint4 g_tab[4][1024];

// ---------------------------------------------------------------------------
// Kernel 1: transpose lgn (B,C,H,W) -> (B,H,W,C), tiled via shared memory.
// ---------------------------------------------------------------------------
__global__ void transpose_lgn_kernel(const float* __restrict__ lgn) {
    __shared__ float sh[64][33];
    const int x0  = blockIdx.x * 32;
    const int y   = blockIdx.y;
    const int b   = blockIdx.z;
    const int tid = threadIdx.x;

    const int cL = tid >> 5, xL = tid & 31;
#pragma unroll
    for (int r = 0; r < 8; r++) {
        const int c = cL + r * 8;
        sh[c][xL] = lgn[(((b * 64 + c) * 64 + y) * 64) + x0 + xL];
    }
    __syncthreads();

    const int cS = tid & 63, xb = tid >> 6;
#pragma unroll
    for (int r = 0; r < 8; r++) {
        const int x = xb + r * 4;
        g_lgn_cl[(((b * 64 + y) * 64 + (x0 + x)) * 64) + cS] = sh[cS][x];
    }
}

__device__ __forceinline__ float dot4(float4 a, float4 b) {
    return a.x * b.x + a.y * b.y + a.z * b.z + a.w * b.w;
}
__device__ __forceinline__ float4 rv(unsigned int a, unsigned int b) {
    const float2 lo = __half22float2(*(const __half2*)&a);
    const float2 hi = __half22float2(*(const __half2*)&b);
    return make_float4(lo.x, lo.y, hi.x, hi.y);
}
__device__ __forceinline__ unsigned int pk(float a, float b) {
    __half2 h = __floats2half2_rn(a, b);
    return *(unsigned int*)&h;
}

// ---------------------------------------------------------------------------
// Kernel T: build fp16 tables once per batch.
// Grid = 4 (batch), block = 256 = 16 rows x 16 nv. Thread (row, nv) computes
// Cy (z interp of coefy), folds R = Cy @ Cr[row], packs R and Cx[row] to fp16.
// Unit layout identical to what the main kernel expects:
//   unit(row,nv,h) at index row*32 + nv*2 + (h ^ ((nv>>2)&1)), h in {0,1}:
//   srh: u.x=pk(R[2h][0],R[2h][1]) u.y=pk(R[2h][2],R[2h][3]) u.z/u.w = R[2h+1]
//   sxh: same with Cx rows (slot = 2h, 2h+1).
// ---------------------------------------------------------------------------
__global__ void build_tables_kernel(
    const float* __restrict__ theta,
    const float* __restrict__ coefx, const float* __restrict__ coefy,
    const float* __restrict__ coefr)
{
    const int b   = blockIdx.x;
    const int tid = threadIdx.x;
    const int nv  = tid & 15;
    const int row = tid >> 4;
    const int hswz = (nv >> 2) & 1;
    const int nv2  = nv * 2;

    const float zc  = theta[b] / 3.14159265358979323846f;
    const float gz  = (zc + 1.0f) * 8.0f - 0.5f;
    const float z0f = floorf(gz);
    const int   z0  = (int)z0f;
    const float wz1 = gz - z0f;
    const float wz0e = (z0 >= 0 && z0 <= 15) ? (1.0f - wz1) : 0.0f;
    const float wz1e = (z0 + 1 >= 0 && z0 + 1 <= 15) ? wz1 : 0.0f;
    const int iz0 = min(max(z0, 0), 15);
    const int iz1 = min(max(z0 + 1, 0), 15);

    // Cy[k][j] = interp_z coefy[nv][k][j][:]
    float Cyv[4][4];
#pragma unroll
    for (int k = 0; k < 4; k++)
#pragma unroll
        for (int j = 0; j < 4; j++) {
            const int base = ((nv * 4 + k) * 4 + j) * 16;
            Cyv[k][j] = wz0e * coefy[base + iz0] + wz1e * coefy[base + iz1];
        }

    // S[kp][l] = coefr[nv][kp][l][row];  R[k][l] = sum_kp Cy[k][kp]*S[kp][l]
    float R[4][4];
#pragma unroll
    for (int k = 0; k < 4; k++)
#pragma unroll
        for (int l = 0; l < 4; l++) R[k][l] = 0.0f;
#pragma unroll
    for (int kp = 0; kp < 4; kp++)
#pragma unroll
        for (int l = 0; l < 4; l++) {
            const float s = coefr[((nv * 4 + kp) * 4 + l) * 16 + row];
#pragma unroll
            for (int k = 0; k < 4; k++) R[k][l] += Cyv[k][kp] * s;
        }

#pragma unroll
    for (int h = 0; h < 2; h++) {
        uint4 u;
        u.x = pk(R[2*h][0],   R[2*h][1]);
        u.y = pk(R[2*h][2],   R[2*h][3]);
        u.z = pk(R[2*h+1][0], R[2*h+1][1]);
        u.w = pk(R[2*h+1][2], R[2*h+1][3]);
        g_tab[b][row * 32 + nv2 + (h ^ hswz)] = u;

        // Cx rows: CA[l] = coefx[nv][2h][l][row], CB[l] = coefx[nv][2h+1][l][row]
        float CA[4], CB[4];
#pragma unroll
        for (int l = 0; l < 4; l++) {
            CA[l] = coefx[((nv * 4 + 2*h)     * 4 + l) * 16 + row];
            CB[l] = coefx[((nv * 4 + 2*h + 1) * 4 + l) * 16 + row];
        }
        uint4 v;
        v.x = pk(CA[0], CA[1]); v.y = pk(CA[2], CA[3]);
        v.z = pk(CB[0], CB[1]); v.w = pk(CB[2], CB[3]);
        g_tab[b][512 + row * 32 + nv2 + (h ^ hswz)] = v;
    }
}

// ---------------------------------------------------------------------------
// Kernel 2: main fused compute.
// Block = 256 threads = 16 pixels x 16 nv.  Thread: pl = tid>>4, nv = tid&15.
// Prologue = coalesced 16KB table copy from g_tab[b] (4 LDG.128 + 4 STS.128
// per thread, one sync). Mainloop: branchless taps, validity folded into
// y-stage weights, hoisted per-row lgn gathers (MLP=3), conflict-free fp16
// table LDS. Output staged in dedicated smem, coalesced stores.
// launch_bounds(256,5): 48 regs -> 5 blocks/SM = 40 warps (62.5% occ);
// smem 16KB + 4.4KB ~ 20.6KB -> smem allows 5+.
// ---------------------------------------------------------------------------
__global__ __launch_bounds__(256, 5) void seprot_main_kernel(
    const float* __restrict__ grid1, const float* __restrict__ grid2,
    float* __restrict__ out)
{
    __shared__ uint4 tab[1024];        // srh = tab[0..511], sxh = tab[512..1023]
    __shared__ float so[64 * 17];      // output staging

    const int tid = threadIdx.x;
    const int b   = blockIdx.x >> 8;   // 256 blocks per batch

    // coalesced table load: 4 uint4 per thread
#pragma unroll
    for (int it = 0; it < 4; it++) {
        const int i = tid + it * 256;
        tab[i] = g_tab[b][i];
    }
    __syncthreads();

    const int nv   = tid & 15;
    const int hswz = (nv >> 2) & 1;
    const int nv4  = nv * 4;
    const int nv2  = nv * 2;
    const int pl   = tid >> 4;                 // pixel within block, 0..15
    const int P    = blockIdx.x * 16 + pl;     // global pixel id

    const uint4* srh = tab;
    const uint4* sxh = tab + 512;

    const float2 g2 = ((const float2*)grid2)[P];   // warp-broadcast (2 addrs)
    const float fx = rintf((g2.x + 1.0f) * 32.0f - 0.5f);
    const float fy = rintf((g2.y + 1.0f) * 32.0f - 0.5f);
    const bool qv = (fx >= 0.0f) && (fx <= 63.0f) && (fy >= 0.0f) && (fy <= 63.0f);

    float acc0 = 0.0f, acc1 = 0.0f, acc2 = 0.0f, acc3 = 0.0f;

    if (qv) {
        const int qx = (int)fx, qy = (int)fy;
        const float4* lbase = (const float4*)g_lgn_cl + (size_t)b * (4096 * 16);
        const float2* g1base = (const float2*)grid1 + b * 4096;

        const int txc0 = min(max(qx - 1, 0), 63);
        const int txc1 = qx;
        const int txc2 = min(max(qx + 1, 0), 63);

#pragma unroll
        for (int di = -1; di <= 1; di++) {
            const int ty   = qy + di;
            const float rowv = ((unsigned)ty < 64u) ? 1.0f : 0.0f;
            const int tyc  = min(max(ty, 0), 63);

            float4 Lr[3];
            Lr[0] = lbase[(tyc * 64 + txc0) * 16 + nv];
            Lr[1] = lbase[(tyc * 64 + txc1) * 16 + nv];
            Lr[2] = lbase[(tyc * 64 + txc2) * 16 + nv];
            float2 g1r[3];
            g1r[0] = g1base[tyc * 64 + txc0];
            g1r[1] = g1base[tyc * 64 + txc1];
            g1r[2] = g1base[tyc * 64 + txc2];

#pragma unroll
            for (int dj = 0; dj < 3; dj++) {
                const int tx = qx + dj - 1;
                const float vm = rowv * (((unsigned)tx < 64u) ? 1.0f : 0.0f);

                const float dx = g2.x - g1r[dj].x;
                const float dy = g2.y - g1r[dj].y;

                // ---- x-axis interp over folded table ----
                const float gx  = (dx + 1.0f) * 8.0f - 0.5f;
                const float x0f = floorf(gx);
                const int   x0  = (int)x0f;
                const float wx1 = gx - x0f;
                const float wx0e = (x0 >= 0 && x0 <= 15) ? (1.0f - wx1) : 0.0f;
                const float wx1e = (x0 + 1 >= 0 && x0 + 1 <= 15) ? wx1 : 0.0f;
                const int ix0 = min(max(x0, 0), 15);
                const int ix1 = min(max(x0 + 1, 0), 15);

                const float4 L = Lr[dj];

                const uint4 U0a = srh[ix0 * 32 + nv2 + (0 ^ hswz)];
                const uint4 U0b = srh[ix0 * 32 + nv2 + (1 ^ hswz)];
                const uint4 U1a = srh[ix1 * 32 + nv2 + (0 ^ hswz)];
                const uint4 U1b = srh[ix1 * 32 + nv2 + (1 ^ hswz)];

                const float u0 = wx0e * dot4(rv(U0a.x, U0a.y), L)
                               + wx1e * dot4(rv(U1a.x, U1a.y), L);
                const float u1 = wx0e * dot4(rv(U0a.z, U0a.w), L)
                               + wx1e * dot4(rv(U1a.z, U1a.w), L);
                const float u2 = wx0e * dot4(rv(U0b.x, U0b.y), L)
                               + wx1e * dot4(rv(U1b.x, U1b.y), L);
                const float u3 = wx0e * dot4(rv(U0b.z, U0b.w), L)
                               + wx1e * dot4(rv(U1b.z, U1b.w), L);
                const float4 u4 = make_float4(u0, u1, u2, u3);

                // ---- y-axis interp over Cx, validity folded into weights ----
                const float gy  = (dy + 1.0f) * 8.0f - 0.5f;
                const float y0f = floorf(gy);
                const int   y0  = (int)y0f;
                const float wy1 = gy - y0f;
                const float wy0e = vm * ((y0 >= 0 && y0 <= 15) ? (1.0f - wy1) : 0.0f);
                const float wy1e = vm * ((y0 + 1 >= 0 && y0 + 1 <= 15) ? wy1 : 0.0f);
                const int iy0 = min(max(y0, 0), 15);
                const int iy1 = min(max(y0 + 1, 0), 15);

                const uint4 V0a = sxh[iy0 * 32 + nv2 + (0 ^ hswz)];
                const uint4 V0b = sxh[iy0 * 32 + nv2 + (1 ^ hswz)];
                const uint4 V1a = sxh[iy1 * 32 + nv2 + (0 ^ hswz)];
                const uint4 V1b = sxh[iy1 * 32 + nv2 + (1 ^ hswz)];

                acc0 += wy0e * dot4(rv(V0a.x, V0a.y), u4)
                      + wy1e * dot4(rv(V1a.x, V1a.y), u4);
                acc1 += wy0e * dot4(rv(V0a.z, V0a.w), u4)
                      + wy1e * dot4(rv(V1a.z, V1a.w), u4);
                acc2 += wy0e * dot4(rv(V0b.x, V0b.y), u4)
                      + wy1e * dot4(rv(V1b.x, V1b.y), u4);
                acc3 += wy0e * dot4(rv(V0b.z, V0b.w), u4)
                      + wy1e * dot4(rv(V1b.z, V1b.w), u4);
            }
        }
    }

    // ---- stage outputs in smem, then coalesced stores ----
    so[(nv4 + 0) * 17 + pl] = acc0;
    so[(nv4 + 1) * 17 + pl] = acc1;
    so[(nv4 + 2) * 17 + pl] = acc2;
    so[(nv4 + 3) * 17 + pl] = acc3;
    __syncthreads();

    // out layout (B, 64, 64, 64): 16 consecutive pixels per block, same batch
    const int rem0 = (blockIdx.x & 255) * 16;
    float* obase = out + (size_t)b * 64 * 4096 + rem0;
#pragma unroll
    for (int i2 = 0; i2 < 4; i2++) {
        const int idx = tid + i2 * 256;
        const int c = idx >> 4, px = idx & 15;
        obase[(size_t)c * 4096 + px] = so[c * 17 + px];
    }
}

extern "C" void kernel_launch(void* const* d_in, const int* in_sizes, int n_in,
                              void* d_out, int out_size) {
    const float* grid1 = (const float*)d_in[0];
    const float* grid2 = (const float*)d_in[1];
    const float* theta = (const float*)d_in[2];
    const float* lgn   = (const float*)d_in[3];
    const float* coefx = (const float*)d_in[4];
    const float* coefy = (const float*)d_in[5];
    const float* coefr = (const float*)d_in[6];
    float* out = (float*)d_out;

    transpose_lgn_kernel<<<dim3(2, 64, 4), 256>>>(lgn);
    build_tables_kernel<<<4, 256>>>(theta, coefx, coefy, coefr);
    seprot_main_kernel<<<1024, 256>>>(grid1, grid2, out);
}

// round 11
// speedup vs baseline: 1.5945x; 1.0667x over previous
#include <cuda_runtime.h>
#include <cuda_fp16.h>

// Scratch: lgn transposed to channel-last [b][y][x][c] (4*64*64*64 f32 = 4MB)
__device__ float g_lgn_cl[4 * 64 * 64 * 64];
// Precomputed fp16 tables per batch: [b][0..511]=srh (folded Cy@Cr), [512..1023]=sxh (Cx)
__device__ uint4 g_tab[4][1024];

__device__ __forceinline__ float dot4(float4 a, float4 b) {
    return a.x * b.x + a.y * b.y + a.z * b.z + a.w * b.w;
}
__device__ __forceinline__ float4 rv(unsigned int a, unsigned int b) {
    const float2 lo = __half22float2(*(const __half2*)&a);
    const float2 hi = __half22float2(*(const __half2*)&b);
    return make_float4(lo.x, lo.y, hi.x, hi.y);
}
__device__ __forceinline__ unsigned int pk(float a, float b) {
    __half2 h = __floats2half2_rn(a, b);
    return *(unsigned int*)&h;
}

// ---------------------------------------------------------------------------
// Kernel 1 (fused prep): blocks 0..255 transpose lgn (B,C,H,W)->(B,H,W,C)
// with float4 global accesses on both sides; blocks 256..259 build the fp16
// coefficient tables (one block per batch).
// ---------------------------------------------------------------------------
__global__ __launch_bounds__(256) void prep_kernel(
    const float* __restrict__ lgn, const float* __restrict__ theta,
    const float* __restrict__ coefx, const float* __restrict__ coefy,
    const float* __restrict__ coefr)
{
    const int blk = blockIdx.x;
    const int t   = threadIdx.x;

    if (blk < 256) {
        // ---- transpose one (b,y) slice: 64 channels x 64 x ----
        __shared__ float tile[64][65];
        const int b = blk >> 6, y = blk & 63;
        const float* src = lgn + ((size_t)(b * 64) * 64 + y) * 64;  // + c*4096 + x

        // load: 4 x LDG.128 per thread (x-contiguous), scalar STS
#pragma unroll
        for (int r = 0; r < 4; r++) {
            const int g  = r * 256 + t;
            const int c  = g >> 4;         // 0..63
            const int xq = g & 15;         // float4 index along x
            const float4 v = *(const float4*)(src + (size_t)c * 4096 + xq * 4);
            tile[c][xq * 4 + 0] = v.x;
            tile[c][xq * 4 + 1] = v.y;
            tile[c][xq * 4 + 2] = v.z;
            tile[c][xq * 4 + 3] = v.w;
        }
        __syncthreads();

        // store: gather 4 channels per thread, STG.128 with c contiguous
        float* dst = g_lgn_cl + ((size_t)(b * 64) + y) * 4096;      // + x*64 + c
#pragma unroll
        for (int r = 0; r < 4; r++) {
            const int g  = r * 256 + t;
            const int x  = g >> 4;         // 0..63
            const int cq = g & 15;         // float4 index along c
            float4 v;
            v.x = tile[cq * 4 + 0][x];
            v.y = tile[cq * 4 + 1][x];
            v.z = tile[cq * 4 + 2][x];
            v.w = tile[cq * 4 + 3][x];
            *(float4*)(dst + (size_t)x * 64 + cq * 4) = v;
        }
    } else {
        // ---- build fp16 tables for batch b ----
        const int b   = blk - 256;
        const int nv  = t & 15;
        const int row = t >> 4;
        const int hswz = (nv >> 2) & 1;
        const int nv2  = nv * 2;

        const float zc  = theta[b] / 3.14159265358979323846f;
        const float gz  = (zc + 1.0f) * 8.0f - 0.5f;
        const float z0f = floorf(gz);
        const int   z0  = (int)z0f;
        const float wz1 = gz - z0f;
        const float wz0e = (z0 >= 0 && z0 <= 15) ? (1.0f - wz1) : 0.0f;
        const float wz1e = (z0 + 1 >= 0 && z0 + 1 <= 15) ? wz1 : 0.0f;
        const int iz0 = min(max(z0, 0), 15);
        const int iz1 = min(max(z0 + 1, 0), 15);

        float Cyv[4][4];
#pragma unroll
        for (int k = 0; k < 4; k++)
#pragma unroll
            for (int j = 0; j < 4; j++) {
                const int base = ((nv * 4 + k) * 4 + j) * 16;
                Cyv[k][j] = wz0e * coefy[base + iz0] + wz1e * coefy[base + iz1];
            }

        float R[4][4];
#pragma unroll
        for (int k = 0; k < 4; k++)
#pragma unroll
            for (int l = 0; l < 4; l++) R[k][l] = 0.0f;
#pragma unroll
        for (int kp = 0; kp < 4; kp++)
#pragma unroll
            for (int l = 0; l < 4; l++) {
                const float s = coefr[((nv * 4 + kp) * 4 + l) * 16 + row];
#pragma unroll
                for (int k = 0; k < 4; k++) R[k][l] += Cyv[k][kp] * s;
            }

#pragma unroll
        for (int h = 0; h < 2; h++) {
            uint4 u;
            u.x = pk(R[2*h][0],   R[2*h][1]);
            u.y = pk(R[2*h][2],   R[2*h][3]);
            u.z = pk(R[2*h+1][0], R[2*h+1][1]);
            u.w = pk(R[2*h+1][2], R[2*h+1][3]);
            g_tab[b][row * 32 + nv2 + (h ^ hswz)] = u;

            float CA[4], CB[4];
#pragma unroll
            for (int l = 0; l < 4; l++) {
                CA[l] = coefx[((nv * 4 + 2*h)     * 4 + l) * 16 + row];
                CB[l] = coefx[((nv * 4 + 2*h + 1) * 4 + l) * 16 + row];
            }
            uint4 v;
            v.x = pk(CA[0], CA[1]); v.y = pk(CA[2], CA[3]);
            v.z = pk(CB[0], CB[1]); v.w = pk(CB[2], CB[3]);
            g_tab[b][512 + row * 32 + nv2 + (h ^ hswz)] = v;
        }
    }
}

// ---------------------------------------------------------------------------
// Kernel 2: main fused compute (unchanged from R9 — verified 26us path).
// Block = 256 threads = 16 pixels x 16 nv.  Thread: pl = tid>>4, nv = tid&15.
// ---------------------------------------------------------------------------
__global__ __launch_bounds__(256, 5) void seprot_main_kernel(
    const float* __restrict__ grid1, const float* __restrict__ grid2,
    float* __restrict__ out)
{
    __shared__ uint4 tab[1024];        // srh = tab[0..511], sxh = tab[512..1023]
    __shared__ float so[64 * 17];      // output staging

    const int tid = threadIdx.x;
    const int b   = blockIdx.x >> 8;   // 256 blocks per batch

#pragma unroll
    for (int it = 0; it < 4; it++) {
        const int i = tid + it * 256;
        tab[i] = g_tab[b][i];
    }
    __syncthreads();

    const int nv   = tid & 15;
    const int hswz = (nv >> 2) & 1;
    const int nv4  = nv * 4;
    const int nv2  = nv * 2;
    const int pl   = tid >> 4;                 // pixel within block, 0..15
    const int P    = blockIdx.x * 16 + pl;     // global pixel id

    const uint4* srh = tab;
    const uint4* sxh = tab + 512;

    const float2 g2 = ((const float2*)grid2)[P];   // warp-broadcast (2 addrs)
    const float fx = rintf((g2.x + 1.0f) * 32.0f - 0.5f);
    const float fy = rintf((g2.y + 1.0f) * 32.0f - 0.5f);
    const bool qv = (fx >= 0.0f) && (fx <= 63.0f) && (fy >= 0.0f) && (fy <= 63.0f);

    float acc0 = 0.0f, acc1 = 0.0f, acc2 = 0.0f, acc3 = 0.0f;

    if (qv) {
        const int qx = (int)fx, qy = (int)fy;
        const float4* lbase = (const float4*)g_lgn_cl + (size_t)b * (4096 * 16);
        const float2* g1base = (const float2*)grid1 + b * 4096;

        const int txc0 = min(max(qx - 1, 0), 63);
        const int txc1 = qx;
        const int txc2 = min(max(qx + 1, 0), 63);

#pragma unroll
        for (int di = -1; di <= 1; di++) {
            const int ty   = qy + di;
            const float rowv = ((unsigned)ty < 64u) ? 1.0f : 0.0f;
            const int tyc  = min(max(ty, 0), 63);

            float4 Lr[3];
            Lr[0] = lbase[(tyc * 64 + txc0) * 16 + nv];
            Lr[1] = lbase[(tyc * 64 + txc1) * 16 + nv];
            Lr[2] = lbase[(tyc * 64 + txc2) * 16 + nv];
            float2 g1r[3];
            g1r[0] = g1base[tyc * 64 + txc0];
            g1r[1] = g1base[tyc * 64 + txc1];
            g1r[2] = g1base[tyc * 64 + txc2];

#pragma unroll
            for (int dj = 0; dj < 3; dj++) {
                const int tx = qx + dj - 1;
                const float vm = rowv * (((unsigned)tx < 64u) ? 1.0f : 0.0f);

                const float dx = g2.x - g1r[dj].x;
                const float dy = g2.y - g1r[dj].y;

                // ---- x-axis interp over folded table ----
                const float gx  = (dx + 1.0f) * 8.0f - 0.5f;
                const float x0f = floorf(gx);
                const int   x0  = (int)x0f;
                const float wx1 = gx - x0f;
                const float wx0e = (x0 >= 0 && x0 <= 15) ? (1.0f - wx1) : 0.0f;
                const float wx1e = (x0 + 1 >= 0 && x0 + 1 <= 15) ? wx1 : 0.0f;
                const int ix0 = min(max(x0, 0), 15);
                const int ix1 = min(max(x0 + 1, 0), 15);

                const float4 L = Lr[dj];

                const uint4 U0a = srh[ix0 * 32 + nv2 + (0 ^ hswz)];
                const uint4 U0b = srh[ix0 * 32 + nv2 + (1 ^ hswz)];
                const uint4 U1a = srh[ix1 * 32 + nv2 + (0 ^ hswz)];
                const uint4 U1b = srh[ix1 * 32 + nv2 + (1 ^ hswz)];

                const float u0 = wx0e * dot4(rv(U0a.x, U0a.y), L)
                               + wx1e * dot4(rv(U1a.x, U1a.y), L);
                const float u1 = wx0e * dot4(rv(U0a.z, U0a.w), L)
                               + wx1e * dot4(rv(U1a.z, U1a.w), L);
                const float u2 = wx0e * dot4(rv(U0b.x, U0b.y), L)
                               + wx1e * dot4(rv(U1b.x, U1b.y), L);
                const float u3 = wx0e * dot4(rv(U0b.z, U0b.w), L)
                               + wx1e * dot4(rv(U1b.z, U1b.w), L);
                const float4 u4 = make_float4(u0, u1, u2, u3);

                // ---- y-axis interp over Cx, validity folded into weights ----
                const float gy  = (dy + 1.0f) * 8.0f - 0.5f;
                const float y0f = floorf(gy);
                const int   y0  = (int)y0f;
                const float wy1 = gy - y0f;
                const float wy0e = vm * ((y0 >= 0 && y0 <= 15) ? (1.0f - wy1) : 0.0f);
                const float wy1e = vm * ((y0 + 1 >= 0 && y0 + 1 <= 15) ? wy1 : 0.0f);
                const int iy0 = min(max(y0, 0), 15);
                const int iy1 = min(max(y0 + 1, 0), 15);

                const uint4 V0a = sxh[iy0 * 32 + nv2 + (0 ^ hswz)];
                const uint4 V0b = sxh[iy0 * 32 + nv2 + (1 ^ hswz)];
                const uint4 V1a = sxh[iy1 * 32 + nv2 + (0 ^ hswz)];
                const uint4 V1b = sxh[iy1 * 32 + nv2 + (1 ^ hswz)];

                acc0 += wy0e * dot4(rv(V0a.x, V0a.y), u4)
                      + wy1e * dot4(rv(V1a.x, V1a.y), u4);
                acc1 += wy0e * dot4(rv(V0a.z, V0a.w), u4)
                      + wy1e * dot4(rv(V1a.z, V1a.w), u4);
                acc2 += wy0e * dot4(rv(V0b.x, V0b.y), u4)
                      + wy1e * dot4(rv(V1b.x, V1b.y), u4);
                acc3 += wy0e * dot4(rv(V0b.z, V0b.w), u4)
                      + wy1e * dot4(rv(V1b.z, V1b.w), u4);
            }
        }
    }

    // ---- stage outputs in smem, then coalesced stores ----
    so[(nv4 + 0) * 17 + pl] = acc0;
    so[(nv4 + 1) * 17 + pl] = acc1;
    so[(nv4 + 2) * 17 + pl] = acc2;
    so[(nv4 + 3) * 17 + pl] = acc3;
    __syncthreads();

    // out layout (B, 64, 64, 64): 16 consecutive pixels per block, same batch
    const int rem0 = (blockIdx.x & 255) * 16;
    float* obase = out + (size_t)b * 64 * 4096 + rem0;
#pragma unroll
    for (int i2 = 0; i2 < 4; i2++) {
        const int idx = tid + i2 * 256;
        const int c = idx >> 4, px = idx & 15;
        obase[(size_t)c * 4096 + px] = so[c * 17 + px];
    }
}

extern "C" void kernel_launch(void* const* d_in, const int* in_sizes, int n_in,
                              void* d_out, int out_size) {
    const float* grid1 = (const float*)d_in[0];
    const float* grid2 = (const float*)d_in[1];
    const float* theta = (const float*)d_in[2];
    const float* lgn   = (const float*)d_in[3];
    const float* coefx = (const float*)d_in[4];
    const float* coefy = (const float*)d_in[5];
    const float* coefr = (const float*)d_in[6];
    float* out = (float*)d_out;

    prep_kernel<<<260, 256>>>(lgn, theta, coefx, coefy, coefr);
    seprot_main_kernel<<<1024, 256>>>(grid1, grid2, out);
}

// round 12
// speedup vs baseline: 1.8079x; 1.1339x over previous
#include <cuda_runtime.h>
#include <cuda_fp16.h>

// Scratch: lgn transposed to channel-last [b][y][x][c] (4*64*64*64 f32 = 4MB)
__device__ float g_lgn_cl[4 * 64 * 64 * 64];
// Precomputed fp16 tables per batch: [b][0..511]=srh (folded Cy@Cr), [512..1023]=sxh (Cx)
__device__ uint4 g_tab[4][1024];

__device__ __forceinline__ float dot4(float4 a, float4 b) {
    return a.x * b.x + a.y * b.y + a.z * b.z + a.w * b.w;
}
__device__ __forceinline__ float4 rv(unsigned int a, unsigned int b) {
    const float2 lo = __half22float2(*(const __half2*)&a);
    const float2 hi = __half22float2(*(const __half2*)&b);
    return make_float4(lo.x, lo.y, hi.x, hi.y);
}
__device__ __forceinline__ unsigned int pk(float a, float b) {
    __half2 h = __floats2half2_rn(a, b);
    return *(unsigned int*)&h;
}
// broadcast one float into a half2 word (single cvt.rn.f16x2.f32)
__device__ __forceinline__ unsigned int h2bc(float w) {
    unsigned int r;
    asm("cvt.rn.f16x2.f32 %0, %1, %1;" : "=r"(r) : "f"(w));
    return r;
}
// fp16 corner blend: w0*a + w1*b per half lane (HMUL2 + HFMA2)
__device__ __forceinline__ unsigned int hblend(unsigned int a, unsigned int b,
                                               unsigned int w0, unsigned int w1) {
    const __half2 r = __hfma2(*(const __half2*)&w0, *(const __half2*)&a,
                              __hmul2(*(const __half2*)&w1, *(const __half2*)&b));
    return *(const unsigned int*)&r;
}

// ---------------------------------------------------------------------------
// Kernel 1 (fused prep): blocks 0..255 transpose lgn (B,C,H,W)->(B,H,W,C)
// with float4 global accesses on both sides; blocks 256..259 build the fp16
// coefficient tables (one block per batch).
// ---------------------------------------------------------------------------
__global__ __launch_bounds__(256) void prep_kernel(
    const float* __restrict__ lgn, const float* __restrict__ theta,
    const float* __restrict__ coefx, const float* __restrict__ coefy,
    const float* __restrict__ coefr)
{
    const int blk = blockIdx.x;
    const int t   = threadIdx.x;

    if (blk < 256) {
        __shared__ float tile[64][65];
        const int b = blk >> 6, y = blk & 63;
        const float* src = lgn + ((size_t)(b * 64) * 64 + y) * 64;  // + c*4096 + x

#pragma unroll
        for (int r = 0; r < 4; r++) {
            const int g  = r * 256 + t;
            const int c  = g >> 4;
            const int xq = g & 15;
            const float4 v = *(const float4*)(src + (size_t)c * 4096 + xq * 4);
            tile[c][xq * 4 + 0] = v.x;
            tile[c][xq * 4 + 1] = v.y;
            tile[c][xq * 4 + 2] = v.z;
            tile[c][xq * 4 + 3] = v.w;
        }
        __syncthreads();

        float* dst = g_lgn_cl + ((size_t)(b * 64) + y) * 4096;      // + x*64 + c
#pragma unroll
        for (int r = 0; r < 4; r++) {
            const int g  = r * 256 + t;
            const int x  = g >> 4;
            const int cq = g & 15;
            float4 v;
            v.x = tile[cq * 4 + 0][x];
            v.y = tile[cq * 4 + 1][x];
            v.z = tile[cq * 4 + 2][x];
            v.w = tile[cq * 4 + 3][x];
            *(float4*)(dst + (size_t)x * 64 + cq * 4) = v;
        }
    } else {
        const int b   = blk - 256;
        const int nv  = t & 15;
        const int row = t >> 4;
        const int hswz = (nv >> 2) & 1;
        const int nv2  = nv * 2;

        const float zc  = theta[b] / 3.14159265358979323846f;
        const float gz  = (zc + 1.0f) * 8.0f - 0.5f;
        const float z0f = floorf(gz);
        const int   z0  = (int)z0f;
        const float wz1 = gz - z0f;
        const float wz0e = (z0 >= 0 && z0 <= 15) ? (1.0f - wz1) : 0.0f;
        const float wz1e = (z0 + 1 >= 0 && z0 + 1 <= 15) ? wz1 : 0.0f;
        const int iz0 = min(max(z0, 0), 15);
        const int iz1 = min(max(z0 + 1, 0), 15);

        float Cyv[4][4];
#pragma unroll
        for (int k = 0; k < 4; k++)
#pragma unroll
            for (int j = 0; j < 4; j++) {
                const int base = ((nv * 4 + k) * 4 + j) * 16;
                Cyv[k][j] = wz0e * coefy[base + iz0] + wz1e * coefy[base + iz1];
            }

        float R[4][4];
#pragma unroll
        for (int k = 0; k < 4; k++)
#pragma unroll
            for (int l = 0; l < 4; l++) R[k][l] = 0.0f;
#pragma unroll
        for (int kp = 0; kp < 4; kp++)
#pragma unroll
            for (int l = 0; l < 4; l++) {
                const float s = coefr[((nv * 4 + kp) * 4 + l) * 16 + row];
#pragma unroll
                for (int k = 0; k < 4; k++) R[k][l] += Cyv[k][kp] * s;
            }

#pragma unroll
        for (int h = 0; h < 2; h++) {
            uint4 u;
            u.x = pk(R[2*h][0],   R[2*h][1]);
            u.y = pk(R[2*h][2],   R[2*h][3]);
            u.z = pk(R[2*h+1][0], R[2*h+1][1]);
            u.w = pk(R[2*h+1][2], R[2*h+1][3]);
            g_tab[b][row * 32 + nv2 + (h ^ hswz)] = u;

            float CA[4], CB[4];
#pragma unroll
            for (int l = 0; l < 4; l++) {
                CA[l] = coefx[((nv * 4 + 2*h)     * 4 + l) * 16 + row];
                CB[l] = coefx[((nv * 4 + 2*h + 1) * 4 + l) * 16 + row];
            }
            uint4 v;
            v.x = pk(CA[0], CA[1]); v.y = pk(CA[2], CA[3]);
            v.z = pk(CB[0], CB[1]); v.w = pk(CB[2], CB[3]);
            g_tab[b][512 + row * 32 + nv2 + (h ^ hswz)] = v;
        }
    }
}

// ---------------------------------------------------------------------------
// Kernel 2: main fused compute.
// Block = 256 threads = 16 pixels x 16 nv.  Thread: pl = tid>>4, nv = tid&15.
// Per tap: load 4+4 fp16 table units, blend the two interp corners IN FP16
// (HMUL2/HFMA2, weights broadcast once), convert only the blended matrix to
// fp32 (16 cvt/stage instead of 32), then plain fp32 dots. ~25% fewer
// dynamic instructions than the corner-weighted fp32 dot scheme.
// ---------------------------------------------------------------------------
__global__ __launch_bounds__(256, 5) void seprot_main_kernel(
    const float* __restrict__ grid1, const float* __restrict__ grid2,
    float* __restrict__ out)
{
    __shared__ uint4 tab[1024];        // srh = tab[0..511], sxh = tab[512..1023]
    __shared__ float so[64 * 17];      // output staging

    const int tid = threadIdx.x;
    const int b   = blockIdx.x >> 8;   // 256 blocks per batch

#pragma unroll
    for (int it = 0; it < 4; it++) {
        const int i = tid + it * 256;
        tab[i] = g_tab[b][i];
    }
    __syncthreads();

    const int nv   = tid & 15;
    const int hswz = (nv >> 2) & 1;
    const int nv4  = nv * 4;
    const int nv2  = nv * 2;
    const int pl   = tid >> 4;                 // pixel within block, 0..15
    const int P    = blockIdx.x * 16 + pl;     // global pixel id

    const uint4* srh = tab;
    const uint4* sxh = tab + 512;
    const int s0 = nv2 + (0 ^ hswz);
    const int s1 = nv2 + (1 ^ hswz);

    const float2 g2 = ((const float2*)grid2)[P];   // warp-broadcast (2 addrs)
    const float fx = rintf((g2.x + 1.0f) * 32.0f - 0.5f);
    const float fy = rintf((g2.y + 1.0f) * 32.0f - 0.5f);
    const bool qv = (fx >= 0.0f) && (fx <= 63.0f) && (fy >= 0.0f) && (fy <= 63.0f);

    float acc0 = 0.0f, acc1 = 0.0f, acc2 = 0.0f, acc3 = 0.0f;

    if (qv) {
        const int qx = (int)fx, qy = (int)fy;
        const float4* lbase = (const float4*)g_lgn_cl + (size_t)b * (4096 * 16);
        const float2* g1base = (const float2*)grid1 + b * 4096;

        const int txc0 = min(max(qx - 1, 0), 63);
        const int txc1 = qx;
        const int txc2 = min(max(qx + 1, 0), 63);

#pragma unroll
        for (int di = -1; di <= 1; di++) {
            const int ty   = qy + di;
            const float rowv = ((unsigned)ty < 64u) ? 1.0f : 0.0f;
            const int tyc  = min(max(ty, 0), 63);

            float4 Lr[3];
            Lr[0] = lbase[(tyc * 64 + txc0) * 16 + nv];
            Lr[1] = lbase[(tyc * 64 + txc1) * 16 + nv];
            Lr[2] = lbase[(tyc * 64 + txc2) * 16 + nv];
            float2 g1r[3];
            g1r[0] = g1base[tyc * 64 + txc0];
            g1r[1] = g1base[tyc * 64 + txc1];
            g1r[2] = g1base[tyc * 64 + txc2];

#pragma unroll
            for (int dj = 0; dj < 3; dj++) {
                const int tx = qx + dj - 1;
                const float vm = rowv * (((unsigned)tx < 64u) ? 1.0f : 0.0f);

                const float dx = g2.x - g1r[dj].x;
                const float dy = g2.y - g1r[dj].y;

                // ---- x-axis: blend two corners of folded table in fp16 ----
                const float gx  = (dx + 1.0f) * 8.0f - 0.5f;
                const float x0f = floorf(gx);
                const int   x0  = (int)x0f;
                const float wx1 = gx - x0f;
                const float wx0e = (x0 >= 0 && x0 <= 15) ? (1.0f - wx1) : 0.0f;
                const float wx1e = (x0 + 1 >= 0 && x0 + 1 <= 15) ? wx1 : 0.0f;
                const int ix0 = min(max(x0, 0), 15);
                const int ix1 = min(max(x0 + 1, 0), 15);

                const float4 L = Lr[dj];

                const uint4 A0 = srh[ix0 * 32 + s0];
                const uint4 A1 = srh[ix0 * 32 + s1];
                const uint4 C0 = srh[ix1 * 32 + s0];
                const uint4 C1 = srh[ix1 * 32 + s1];
                const unsigned xw0 = h2bc(wx0e), xw1 = h2bc(wx1e);

                uint4 B0, B1;
                B0.x = hblend(A0.x, C0.x, xw0, xw1);
                B0.y = hblend(A0.y, C0.y, xw0, xw1);
                B0.z = hblend(A0.z, C0.z, xw0, xw1);
                B0.w = hblend(A0.w, C0.w, xw0, xw1);
                B1.x = hblend(A1.x, C1.x, xw0, xw1);
                B1.y = hblend(A1.y, C1.y, xw0, xw1);
                B1.z = hblend(A1.z, C1.z, xw0, xw1);
                B1.w = hblend(A1.w, C1.w, xw0, xw1);

                const float u0 = dot4(rv(B0.x, B0.y), L);
                const float u1 = dot4(rv(B0.z, B0.w), L);
                const float u2 = dot4(rv(B1.x, B1.y), L);
                const float u3 = dot4(rv(B1.z, B1.w), L);
                const float4 u4 = make_float4(u0, u1, u2, u3);

                // ---- y-axis: blend Cx corners in fp16 (validity in weights) --
                const float gy  = (dy + 1.0f) * 8.0f - 0.5f;
                const float y0f = floorf(gy);
                const int   y0  = (int)y0f;
                const float wy1 = gy - y0f;
                const float wy0e = vm * ((y0 >= 0 && y0 <= 15) ? (1.0f - wy1) : 0.0f);
                const float wy1e = vm * ((y0 + 1 >= 0 && y0 + 1 <= 15) ? wy1 : 0.0f);
                const int iy0 = min(max(y0, 0), 15);
                const int iy1 = min(max(y0 + 1, 0), 15);

                const uint4 D0 = sxh[iy0 * 32 + s0];
                const uint4 D1 = sxh[iy0 * 32 + s1];
                const uint4 E0 = sxh[iy1 * 32 + s0];
                const uint4 E1 = sxh[iy1 * 32 + s1];
                const unsigned yw0 = h2bc(wy0e), yw1 = h2bc(wy1e);

                uint4 F0, F1;
                F0.x = hblend(D0.x, E0.x, yw0, yw1);
                F0.y = hblend(D0.y, E0.y, yw0, yw1);
                F0.z = hblend(D0.z, E0.z, yw0, yw1);
                F0.w = hblend(D0.w, E0.w, yw0, yw1);
                F1.x = hblend(D1.x, E1.x, yw0, yw1);
                F1.y = hblend(D1.y, E1.y, yw0, yw1);
                F1.z = hblend(D1.z, E1.z, yw0, yw1);
                F1.w = hblend(D1.w, E1.w, yw0, yw1);

                acc0 += dot4(rv(F0.x, F0.y), u4);
                acc1 += dot4(rv(F0.z, F0.w), u4);
                acc2 += dot4(rv(F1.x, F1.y), u4);
                acc3 += dot4(rv(F1.z, F1.w), u4);
            }
        }
    }

    // ---- stage outputs in smem, then coalesced stores ----
    so[(nv4 + 0) * 17 + pl] = acc0;
    so[(nv4 + 1) * 17 + pl] = acc1;
    so[(nv4 + 2) * 17 + pl] = acc2;
    so[(nv4 + 3) * 17 + pl] = acc3;
    __syncthreads();

    // out layout (B, 64, 64, 64): 16 consecutive pixels per block, same batch
    const int rem0 = (blockIdx.x & 255) * 16;
    float* obase = out + (size_t)b * 64 * 4096 + rem0;
#pragma unroll
    for (int i2 = 0; i2 < 4; i2++) {
        const int idx = tid + i2 * 256;
        const int c = idx >> 4, px = idx & 15;
        obase[(size_t)c * 4096 + px] = so[c * 17 + px];
    }
}

extern "C" void kernel_launch(void* const* d_in, const int* in_sizes, int n_in,
                              void* d_out, int out_size) {
    const float* grid1 = (const float*)d_in[0];
    const float* grid2 = (const float*)d_in[1];
    const float* theta = (const float*)d_in[2];
    const float* lgn   = (const float*)d_in[3];
    const float* coefx = (const float*)d_in[4];
    const float* coefy = (const float*)d_in[5];
    const float* coefr = (const float*)d_in[6];
    float* out = (float*)d_out;

    prep_kernel<<<260, 256>>>(lgn, theta, coefx, coefy, coefr);
    seprot_main_kernel<<<1024, 256>>>(grid1, grid2, out);
}